// round 15
// baseline (speedup 1.0000x reference)
#include <cuda_runtime.h>
#include <cuda_fp16.h>
#include <cuda_fp8.h>
#include <cstdint>
#include <cstddef>

#define TDIM 4096
#define HDIM 2048
#define FDIM 7168

// ---------------- GEMM tile config (fp16 A x fp8 B mma.sync, pair-staged, persistent) ------
#define BM 128
#define BN 256
#define AST 16384                     // A 64-k stage: 128 rows x 128B (fp16)
#define BPAIR 32768                   // B 128-k PAIR buffer: 256 rows x 128B (fp8)
#define B_BASE 65536                  // after 4 A stages
#define SMEMB (B_BASE + 2 * BPAIR)    // 131072

#define N4X (TDIM * HDIM / 4)         // x float4 count
#define NGW (FDIM * HDIM / 16)        // 16-elem k-groups per weight tensor = 917504

// ---------------- scratch (no allocations allowed) ----------------
__device__ __half   d_xh[(size_t)TDIM * HDIM];
__device__ uint8_t  d_w1f8[(size_t)FDIM * HDIM];
__device__ uint8_t  d_w3f8[(size_t)FDIM * HDIM];
__device__ uint8_t  d_w2f8[(size_t)HDIM * FDIM];
__device__ __half   d_gh[(size_t)TDIM * FDIM];
__device__ __half   d_uh[(size_t)TDIM * FDIM];
__device__ __half   d_acth[(size_t)TDIM * FDIM];

// ---------------- helpers ----------------
__device__ __forceinline__ uint32_t smem_u32(const void* p) {
    uint32_t a;
    asm("{ .reg .u64 t; cvta.to.shared.u64 t, %1; cvt.u32.u64 %0, t; }" : "=r"(a) : "l"(p));
    return a;
}
__device__ __forceinline__ void cp_async16(uint32_t dst, const void* src) {
    asm volatile("cp.async.cg.shared.global [%0], [%1], 16;\n" :: "r"(dst), "l"(src));
}
__device__ __forceinline__ void cp_commit() { asm volatile("cp.async.commit_group;\n"); }
template <int N>
__device__ __forceinline__ void cp_wait() { asm volatile("cp.async.wait_group %0;\n" :: "n"(N)); }

__device__ __forceinline__ void ldm_x4(uint32_t* r, uint32_t addr) {
    asm volatile("ldmatrix.sync.aligned.m8n8.x4.shared.b16 {%0,%1,%2,%3}, [%4];"
                 : "=r"(r[0]), "=r"(r[1]), "=r"(r[2]), "=r"(r[3]) : "r"(addr));
}
__device__ __forceinline__ void mma_f16(float* d, const uint32_t* a, const uint32_t* b) {
    asm volatile(
        "mma.sync.aligned.m16n8k16.row.col.f32.f16.f16.f32 "
        "{%0,%1,%2,%3}, {%4,%5,%6,%7}, {%8,%9}, {%0,%1,%2,%3};\n"
        : "+f"(d[0]), "+f"(d[1]), "+f"(d[2]), "+f"(d[3])
        : "r"(a[0]), "r"(a[1]), "r"(a[2]), "r"(a[3]), "r"(b[0]), "r"(b[1]));
}
// 4 packed e4m3 -> two f16x2 regs (lo slot = b0 pair, hi slot = b1 pair)
__device__ __forceinline__ void fp8x4_cvt(uint32_t pb, uint32_t& lo, uint32_t& hi) {
    asm("{ .reg .b16 l, h;\n\t"
        "mov.b32 {l, h}, %2;\n\t"
        "cvt.rn.f16x2.e4m3x2 %0, l;\n\t"
        "cvt.rn.f16x2.e4m3x2 %1, h; }"
        : "=r"(lo), "=r"(hi) : "r"(pb));
}

// ---------------- x convert: fp32 -> fp16, 4 float4 per thread ----------------
__global__ void cvt_x_kernel(const float4* __restrict__ in, uint2* __restrict__ out, int n4) {
    int base = blockIdx.x * (blockDim.x * 4) + threadIdx.x;
    #pragma unroll
    for (int k = 0; k < 4; k++) {
        int i = base + k * blockDim.x;
        if (i < n4) {
            float4 v = in[i];
            __half2 h0 = __floats2half2_rn(v.x, v.y);
            __half2 h1 = __floats2half2_rn(v.z, v.w);
            out[i] = make_uint2(*reinterpret_cast<uint32_t*>(&h0), *reinterpret_cast<uint32_t*>(&h1));
        }
    }
}

// ---------------- weight convert: fp32 -> permuted fp8 (exact: values are e4m3) ----------
// Per 16-k group, byte layout (slot = 2 bytes): slot 2a <- (k=2a,2a+1), slot 2a+1 <- (2a+8,2a+9)
// so that ldmatrix.b16 + cvt yields the exact mma B-fragment pairs.
__device__ __forceinline__ uint8_t f2e4m3(float v) {
    return (uint8_t)__nv_cvt_float_to_fp8(v, __NV_SATFINITE, __NV_E4M3);
}
__global__ void cvt_w8_kernel(const float4* __restrict__ w1, uint4* __restrict__ o1,
                              const float4* __restrict__ w3, uint4* __restrict__ o3,
                              const float4* __restrict__ w2, uint4* __restrict__ o2) {
    int i = blockIdx.x * blockDim.x + threadIdx.x;
    const float4* src; uint4* dst; int j;
    if (i < NGW)            { src = w1; dst = o1; j = i; }
    else if (i < 2 * NGW)   { src = w3; dst = o3; j = i - NGW; }
    else if (i < 3 * NGW)   { src = w2; dst = o2; j = i - 2 * NGW; }
    else return;
    float4 a0 = src[j * 4 + 0], a1 = src[j * 4 + 1], a2 = src[j * 4 + 2], a3 = src[j * 4 + 3];
    float v[16] = {a0.x, a0.y, a0.z, a0.w, a1.x, a1.y, a1.z, a1.w,
                   a2.x, a2.y, a2.z, a2.w, a3.x, a3.y, a3.z, a3.w};
    uint32_t w[4];
    #pragma unroll
    for (int a = 0; a < 4; a++) {
        w[a] = (uint32_t)f2e4m3(v[2 * a])
             | ((uint32_t)f2e4m3(v[2 * a + 1]) << 8)
             | ((uint32_t)f2e4m3(v[2 * a + 8]) << 16)
             | ((uint32_t)f2e4m3(v[2 * a + 9]) << 24);
    }
    dst[j] = make_uint4(w[0], w[1], w[2], w[3]);
}

// ---------------- silu-mul on fp16 inputs; 4 uint2 per thread ----------------
__global__ void silu_mul_h_kernel(const uint2* __restrict__ g, const uint2* __restrict__ u,
                                  uint2* __restrict__ out, int n4) {
    int base = blockIdx.x * (blockDim.x * 4) + threadIdx.x;
    #pragma unroll
    for (int k = 0; k < 4; k++) {
        int i = base + k * blockDim.x;
        if (i < n4) {
            uint2 gv = g[i], uv = u[i];
            __half2 g0 = *reinterpret_cast<__half2*>(&gv.x);
            __half2 g1 = *reinterpret_cast<__half2*>(&gv.y);
            __half2 u0 = *reinterpret_cast<__half2*>(&uv.x);
            __half2 u1 = *reinterpret_cast<__half2*>(&uv.y);
            float a0 = __low2float(g0), a1 = __high2float(g0);
            float a2 = __low2float(g1), a3 = __high2float(g1);
            float r0 = a0 / (1.0f + __expf(-a0)) * __low2float(u0);
            float r1 = a1 / (1.0f + __expf(-a1)) * __high2float(u0);
            float r2 = a2 / (1.0f + __expf(-a2)) * __low2float(u1);
            float r3 = a3 / (1.0f + __expf(-a3)) * __high2float(u1);
            __half2 h0 = __floats2half2_rn(r0, r1);
            __half2 h1 = __floats2half2_rn(r2, r3);
            out[i] = make_uint2(*reinterpret_cast<uint32_t*>(&h0), *reinterpret_cast<uint32_t*>(&h1));
        }
    }
}

// ---------------- persistent GEMM: A fp16 smem, B fp8 smem (halved crossbar traffic) -------
// C[m,n] = sum_kb S[n/128, kb] * sum_{k in kb} A[m,k] * B[n,k]
// B smem: one 256x128B fp8 buffer per K=128 pair. bf path: ldmatrix.b16 on packed fp8,
// then cvt.rn.f16x2.e4m3x2 -> exact fp16 B fragments (identical values to before).
// Scale fold interleaved into the first mma group of each pair (per q sub-group).
__global__ __launch_bounds__(256, 1)
void gemm_f16(const __half* __restrict__ A,
              const uint8_t* __restrict__ B0, const float* __restrict__ S0, void* __restrict__ C0,
              const uint8_t* __restrict__ B1, const float* __restrict__ S1, void* __restrict__ C1,
              int M, int N, int K, int out_half, int nz)
{
    extern __shared__ char smem[];
    const uint32_t sb = smem_u32(smem);
    const int tid = threadIdx.x;
    const int wid = tid >> 5, lane = tid & 31;
    const int wm = wid & 1, wn = wid >> 1;       // 2 x 4 warps, 64x64 warp tiles
    const int mat = lane >> 3, mr = lane & 7;
    const int g = lane >> 2, t4 = lane & 3;

    const int GM = M >> 7;              // M/128 tiles
    const int GN = N >> 8;              // N/256 tiles
    const int NP = K >> 7;              // K=128 pairs == scale blocks
    const int total = GM * GN * nz;

    for (int t = blockIdx.x; t < total; t += gridDim.x) {
        const int z  = t / (GM * GN);
        const int r_ = t - z * (GM * GN);
        const int bn = r_ / GM;
        const int bm = r_ - bn * GM;

        const uint8_t* B = z ? B1 : B0;
        const float*   S = z ? S1 : S0;
        void*          Cv = z ? C1 : C0;

        const __half*  Ab = A + (size_t)bm * BM * K;
        const uint8_t* Bb = B + (size_t)bn * BN * K;
        const float* Srow = S + (size_t)(bn * 2 + (wn >> 1)) * NP;

        // load pair p: A (2 x 16KB fp16 stages) + B (1 x 32KB fp8 pair buffer); ONE commit
        auto load_pair = [&](int p) {
            #pragma unroll
            for (int h = 0; h < 2; h++) {
                const uint32_t ab = sb + ((p & 1) * 2 + h) * AST;
                const int k0 = (p << 7) + (h << 6);
                #pragma unroll
                for (int tt = 0; tt < 4; tt++) {        // A: 1024 x 16B chunks
                    int idx = tid + tt * 256;
                    int row = idx >> 3, c = idx & 7;
                    uint32_t off = (uint32_t)(row << 7) + (c << 4);
                    uint32_t sw = off ^ ((off >> 3) & 0x70);
                    cp_async16(ab + sw, Ab + (size_t)row * K + k0 + c * 8);
                }
            }
            {
                const uint32_t bbuf = sb + B_BASE + (p & 1) * BPAIR;
                #pragma unroll
                for (int tt = 0; tt < 8; tt++) {        // B: 2048 x 16B chunks (256 rows x 128B)
                    int idx = tid + tt * 256;
                    int row = idx >> 3, c = idx & 7;
                    uint32_t off = (uint32_t)(row << 7) + (c << 4);
                    uint32_t sw = off ^ ((off >> 3) & 0x70);
                    cp_async16(bbuf + sw, Bb + (size_t)row * K + (p << 7) + c * 16);
                }
            }
            cp_commit();
        };

        float acc[4][8][4];
        #pragma unroll
        for (int mt = 0; mt < 4; mt++)
            #pragma unroll
            for (int nt = 0; nt < 8; nt++)
                #pragma unroll
                for (int i = 0; i < 4; i++) acc[mt][nt][i] = 0.0f;

        load_pair(0);
        float s_cur = __ldg(Srow);

        for (int p = 0; p < NP; p++) {
            float rr = 1.0f;
            if (p) {                    // entering new scale block (== new pair)
                float sn = __ldg(Srow + p);
                rr = s_cur / sn;
                s_cur = sn;
            }

            cp_wait<0>();               // pair p resident (only group in flight)
            __syncthreads();            // all warps done with pair p-1's buffers

            if (p + 1 < NP) load_pair(p + 1);   // overwrites pair p-1's buffers: safe

            const uint32_t bbuf = sb + B_BASE + (p & 1) * BPAIR;
            #pragma unroll
            for (int h = 0; h < 2; h++) {
                const uint32_t ab = sb + ((p & 1) * 2 + h) * AST;
                #pragma unroll
                for (int ks = 0; ks < 4; ks++) {
                    const int G = h * 4 + ks;           // 16-k group within pair
                    uint32_t af[4][4];
                    #pragma unroll
                    for (int mt = 0; mt < 4; mt++) {
                        int row = wm * 64 + mt * 16 + (mat & 1) * 8 + mr;
                        uint32_t off = (uint32_t)(row << 7) + ks * 32 + (mat >> 1) * 16;
                        uint32_t sw = off ^ ((off >> 3) & 0x70);
                        ldm_x4(af[mt], ab + sw);
                    }
                    #pragma unroll
                    for (int q = 0; q < 2; q++) {
                        uint32_t pb[4];
                        {
                            int nrow = wn * 64 + q * 32 + mat * 8 + mr;
                            uint32_t off = (uint32_t)(nrow << 7) + G * 16;
                            uint32_t sw = off ^ ((off >> 3) & 0x70);
                            ldm_x4(pb, bbuf + sw);
                        }
                        uint32_t bfh[4][2];
                        #pragma unroll
                        for (int j = 0; j < 4; j++) fp8x4_cvt(pb[j], bfh[j][0], bfh[j][1]);

                        if (h == 0 && ks == 0) {
                            // fold interleaved with the pair's first mma of each tile
                            #pragma unroll
                            for (int mt = 0; mt < 4; mt++)
                                #pragma unroll
                                for (int j = 0; j < 4; j++) {
                                    int nt = q * 4 + j;
                                    acc[mt][nt][0] *= rr;
                                    acc[mt][nt][1] *= rr;
                                    acc[mt][nt][2] *= rr;
                                    acc[mt][nt][3] *= rr;
                                    mma_f16(acc[mt][nt], af[mt], &bfh[j][0]);
                                }
                        } else {
                            #pragma unroll
                            for (int mt = 0; mt < 4; mt++)
                                #pragma unroll
                                for (int j = 0; j < 4; j++)
                                    mma_f16(acc[mt][q * 4 + j], af[mt], &bfh[j][0]);
                        }
                    }
                }
            }
        }

        // epilogue: scale by this warp's last block S; fp16 or fp32 stores
        if (out_half) {
            __half* Ch = (__half*)Cv;
            #pragma unroll
            for (int mt = 0; mt < 4; mt++) {
                int r0 = bm * BM + wm * 64 + mt * 16 + g;
                #pragma unroll
                for (int nt = 0; nt < 8; nt++) {
                    int c0 = bn * BN + wn * 64 + nt * 8 + t4 * 2;
                    __half2 h0 = __floats2half2_rn(acc[mt][nt][0] * s_cur, acc[mt][nt][1] * s_cur);
                    __half2 h1 = __floats2half2_rn(acc[mt][nt][2] * s_cur, acc[mt][nt][3] * s_cur);
                    *reinterpret_cast<__half2*>(&Ch[(size_t)r0 * N + c0]) = h0;
                    *reinterpret_cast<__half2*>(&Ch[(size_t)(r0 + 8) * N + c0]) = h1;
                }
            }
        } else {
            float* Cf = (float*)Cv;
            #pragma unroll
            for (int mt = 0; mt < 4; mt++) {
                int r0 = bm * BM + wm * 64 + mt * 16 + g;
                #pragma unroll
                for (int nt = 0; nt < 8; nt++) {
                    int c0 = bn * BN + wn * 64 + nt * 8 + t4 * 2;
                    float2 v0 = make_float2(acc[mt][nt][0] * s_cur, acc[mt][nt][1] * s_cur);
                    float2 v1 = make_float2(acc[mt][nt][2] * s_cur, acc[mt][nt][3] * s_cur);
                    *reinterpret_cast<float2*>(&Cf[(size_t)r0 * N + c0]) = v0;
                    *reinterpret_cast<float2*>(&Cf[(size_t)(r0 + 8) * N + c0]) = v1;
                }
            }
        }
    }
}

// ---------------- launch ----------------
extern "C" void kernel_launch(void* const* d_in, const int* in_sizes, int n_in,
                              void* d_out, int out_size) {
    (void)in_sizes; (void)n_in; (void)out_size;
    const float* x   = (const float*)d_in[0];
    const float* w1q = (const float*)d_in[1];
    const float* w1s = (const float*)d_in[2];
    const float* w3q = (const float*)d_in[3];
    const float* w3s = (const float*)d_in[4];
    const float* w2q = (const float*)d_in[5];
    const float* w2s = (const float*)d_in[6];
    float* out = (float*)d_out;

    __half *xh, *gh, *uh, *acth;
    uint8_t *w1f8, *w3f8, *w2f8;
    cudaGetSymbolAddress((void**)&xh,   d_xh);
    cudaGetSymbolAddress((void**)&w1f8, d_w1f8);
    cudaGetSymbolAddress((void**)&w3f8, d_w3f8);
    cudaGetSymbolAddress((void**)&w2f8, d_w2f8);
    cudaGetSymbolAddress((void**)&gh,   d_gh);
    cudaGetSymbolAddress((void**)&uh,   d_uh);
    cudaGetSymbolAddress((void**)&acth, d_acth);

    int nsm = 148;
    cudaDeviceGetAttribute(&nsm, cudaDevAttrMultiProcessorCount, 0);

    cudaFuncSetAttribute(gemm_f16, cudaFuncAttributeMaxDynamicSharedMemorySize, SMEMB);

    // x -> fp16
    cvt_x_kernel<<<(N4X + 1023) / 1024, 256>>>((const float4*)x, (uint2*)xh, N4X);
    // weights -> permuted fp8 (exact)
    cvt_w8_kernel<<<(3 * NGW + 255) / 256, 256>>>(
        (const float4*)w1q, (uint4*)w1f8,
        (const float4*)w3q, (uint4*)w3f8,
        (const float4*)w2q, (uint4*)w2f8);

    // g = x@w1^T and u = x@w3^T in ONE persistent launch (fp16 outputs)
    {
        const int tiles = (TDIM / BM) * (FDIM / BN) * 2;
        const int grid = tiles < nsm ? tiles : nsm;
        gemm_f16<<<grid, 256, SMEMB>>>(
            xh, w1f8, w1s, gh, w3f8, w3s, uh, TDIM, FDIM, HDIM, 1, 2);
    }

    const int n4f = TDIM * FDIM / 4;
    silu_mul_h_kernel<<<(n4f + 1023) / 1024, 256>>>(
        (const uint2*)gh, (const uint2*)uh, (uint2*)acth, n4f);

    // out = act @ w2^T  (fp32 out, persistent)
    {
        const int tiles = (TDIM / BM) * (HDIM / BN);
        const int grid = tiles < nsm ? tiles : nsm;
        gemm_f16<<<grid, 256, SMEMB>>>(
            acth, w2f8, w2s, out, w2f8, w2s, out, TDIM, HDIM, FDIM, 0, 1);
    }
}

// round 16
// speedup vs baseline: 1.5351x; 1.5351x over previous
#include <cuda_runtime.h>
#include <cuda_fp16.h>
#include <cstdint>
#include <cstddef>

#define TDIM 4096
#define HDIM 2048
#define FDIM 7168

// ---------------- shared GEMM config ----------------
#define STG 4                         // 64-k stages (2 pair-buffers)
#define N4X (TDIM * HDIM / 4)
#define N4W (FDIM * HDIM / 4)

// fused g/u kernel: per 64-k stage: A 16KB + B1 16KB + B3 16KB
#define FST 49152
#define SMEMF (STG / 2 * 2 * FST)     // 196608 (4 stages)

// GEMM3 (R14 layout): per 64-k stage: A 16KB + B 32KB
#define AST 16384
#define BST 32768
#define STB (AST + BST)
#define SMEMB (STG * STB)             // 196608

// ---------------- scratch (no allocations allowed) ----------------
__device__ __half d_xh[(size_t)TDIM * HDIM];
__device__ __half d_w1h[(size_t)FDIM * HDIM];
__device__ __half d_w3h[(size_t)FDIM * HDIM];
__device__ __half d_w2h[(size_t)HDIM * FDIM];
__device__ __half d_acth[(size_t)TDIM * FDIM];

// ---------------- helpers ----------------
__device__ __forceinline__ uint32_t smem_u32(const void* p) {
    uint32_t a;
    asm("{ .reg .u64 t; cvta.to.shared.u64 t, %1; cvt.u32.u64 %0, t; }" : "=r"(a) : "l"(p));
    return a;
}
__device__ __forceinline__ void cp_async16(uint32_t dst, const void* src) {
    asm volatile("cp.async.cg.shared.global [%0], [%1], 16;\n" :: "r"(dst), "l"(src));
}
__device__ __forceinline__ void cp_commit() { asm volatile("cp.async.commit_group;\n"); }
template <int N>
__device__ __forceinline__ void cp_wait() { asm volatile("cp.async.wait_group %0;\n" :: "n"(N)); }

__device__ __forceinline__ void ldm_x4(uint32_t* r, uint32_t addr) {
    asm volatile("ldmatrix.sync.aligned.m8n8.x4.shared.b16 {%0,%1,%2,%3}, [%4];"
                 : "=r"(r[0]), "=r"(r[1]), "=r"(r[2]), "=r"(r[3]) : "r"(addr));
}
__device__ __forceinline__ void mma_f16(float* d, const uint32_t* a, const uint32_t* b) {
    asm volatile(
        "mma.sync.aligned.m16n8k16.row.col.f32.f16.f16.f32 "
        "{%0,%1,%2,%3}, {%4,%5,%6,%7}, {%8,%9}, {%0,%1,%2,%3};\n"
        : "+f"(d[0]), "+f"(d[1]), "+f"(d[2]), "+f"(d[3])
        : "r"(a[0]), "r"(a[1]), "r"(a[2]), "r"(a[3]), "r"(b[0]), "r"(b[1]));
}
__device__ __forceinline__ float silu_f(float v) { return v / (1.0f + __expf(-v)); }

// ---------------- fused convert kernel: x, w1, w3, w2; 4 float4 per thread ----------------
__device__ __forceinline__ void cvt_one(const float4* __restrict__ x,  uint2* __restrict__ xo,
                                        const float4* __restrict__ w1, uint2* __restrict__ w1o,
                                        const float4* __restrict__ w3, uint2* __restrict__ w3o,
                                        const float4* __restrict__ w2, uint2* __restrict__ w2o,
                                        int i) {
    const float4* src; uint2* dst; int j;
    if (i < N4X)               { src = x;  dst = xo;  j = i; }
    else if (i < N4X + N4W)    { src = w1; dst = w1o; j = i - N4X; }
    else if (i < N4X + 2*N4W)  { src = w3; dst = w3o; j = i - N4X - N4W; }
    else                       { src = w2; dst = w2o; j = i - N4X - 2*N4W; }
    float4 v = src[j];
    __half2 h0 = __floats2half2_rn(v.x, v.y);
    __half2 h1 = __floats2half2_rn(v.z, v.w);
    dst[j] = make_uint2(*reinterpret_cast<uint32_t*>(&h0), *reinterpret_cast<uint32_t*>(&h1));
}

__global__ void cvt_all_kernel(const float4* __restrict__ x,  uint2* __restrict__ xo,
                               const float4* __restrict__ w1, uint2* __restrict__ w1o,
                               const float4* __restrict__ w3, uint2* __restrict__ w3o,
                               const float4* __restrict__ w2, uint2* __restrict__ w2o,
                               int n4) {
    int base = blockIdx.x * (blockDim.x * 4) + threadIdx.x;
    #pragma unroll
    for (int k = 0; k < 4; k++) {
        int i = base + k * blockDim.x;
        if (i < n4) cvt_one(x, xo, w1, w1o, w3, w3o, w2, w2o, i);
    }
}

// ============ fused g/u GEMM: act = silu(x@w1^T .* s1) * (x@w3^T .* s3), fp16 out ==========
// Tile: bm (128 rows of x) x bn (128 cols of BOTH w1 and w3). Warp tile 64x32 per matrix.
// Per ks: af x4 (shared) + bf1 x2 + bf3 x2 LDSM, 16 g-mma + 16 u-mma — same issue count and
// crossbar bytes as the validated 128x256 single-matrix mainloop. silu applied in registers.
__global__ __launch_bounds__(256, 1)
void gemm12_fused(const __half* __restrict__ A,
                  const __half* __restrict__ B1, const float* __restrict__ S1,
                  const __half* __restrict__ B3, const float* __restrict__ S3,
                  __half* __restrict__ Act,
                  int M, int N, int K)
{
    extern __shared__ char smem[];
    const uint32_t sb = smem_u32(smem);
    const int tid = threadIdx.x;
    const int wid = tid >> 5, lane = tid & 31;
    const int wm = wid & 1, wn = wid >> 1;       // 2 x 4 warps, 64x32 warp tiles (per matrix)
    const int mat = lane >> 3, mr = lane & 7;
    const int g = lane >> 2, t4 = lane & 3;

    const int GM = M >> 7;              // M/128
    const int GN = N >> 7;              // N/128 (per matrix)
    const int NP = K >> 7;              // K=128 pairs == scale blocks
    const int total = GM * GN;

    for (int t = blockIdx.x; t < total; t += gridDim.x) {
        const int bn = t / GM;
        const int bm = t - bn * GM;

        const __half* Ab  = A  + (size_t)bm * 128 * K;
        const __half* B1b = B1 + (size_t)bn * 128 * K;
        const __half* B3b = B3 + (size_t)bn * 128 * K;
        const float* Srow1 = S1 + (size_t)bn * NP;
        const float* Srow3 = S3 + (size_t)bn * NP;

        // load pair p into 64-k stages (p&1)*2, (p&1)*2+1; each stage: A | B1 | B3; ONE commit
        auto load_pair = [&](int p) {
            #pragma unroll
            for (int h = 0; h < 2; h++) {
                const uint32_t base = sb + ((p & 1) * 2 + h) * FST;
                const int k0 = (p << 7) + (h << 6);
                #pragma unroll
                for (int tt = 0; tt < 4; tt++) {        // A: 1024 x 16B
                    int idx = tid + tt * 256;
                    int row = idx >> 3, c = idx & 7;
                    uint32_t off = (uint32_t)(row << 7) + (c << 4);
                    uint32_t sw = off ^ ((off >> 3) & 0x70);
                    cp_async16(base + sw, Ab + (size_t)row * K + k0 + c * 8);
                }
                #pragma unroll
                for (int tt = 0; tt < 4; tt++) {        // B1: 1024 x 16B
                    int idx = tid + tt * 256;
                    int row = idx >> 3, c = idx & 7;
                    uint32_t off = (uint32_t)(row << 7) + (c << 4);
                    uint32_t sw = off ^ ((off >> 3) & 0x70);
                    cp_async16(base + 16384 + sw, B1b + (size_t)row * K + k0 + c * 8);
                }
                #pragma unroll
                for (int tt = 0; tt < 4; tt++) {        // B3: 1024 x 16B
                    int idx = tid + tt * 256;
                    int row = idx >> 3, c = idx & 7;
                    uint32_t off = (uint32_t)(row << 7) + (c << 4);
                    uint32_t sw = off ^ ((off >> 3) & 0x70);
                    cp_async16(base + 32768 + sw, B3b + (size_t)row * K + k0 + c * 8);
                }
            }
            cp_commit();
        };

        float accg[4][4][4], accu[4][4][4];
        #pragma unroll
        for (int mt = 0; mt < 4; mt++)
            #pragma unroll
            for (int nt = 0; nt < 4; nt++)
                #pragma unroll
                for (int i = 0; i < 4; i++) { accg[mt][nt][i] = 0.0f; accu[mt][nt][i] = 0.0f; }

        load_pair(0);
        float s1_cur = __ldg(Srow1);
        float s3_cur = __ldg(Srow3);

        for (int p = 0; p < NP; p++) {
            float rr1 = 1.0f, rr3 = 1.0f;
            if (p) {
                float sn1 = __ldg(Srow1 + p);
                float sn3 = __ldg(Srow3 + p);
                rr1 = s1_cur / sn1; s1_cur = sn1;
                rr3 = s3_cur / sn3; s3_cur = sn3;
            }

            cp_wait<0>();
            __syncthreads();

            if (p + 1 < NP) load_pair(p + 1);

            #pragma unroll
            for (int h = 0; h < 2; h++) {
                const uint32_t base = sb + ((p & 1) * 2 + h) * FST;
                #pragma unroll
                for (int ks = 0; ks < 4; ks++) {
                    uint32_t af[4][4], bf1[2][4], bf3[2][4];
                    #pragma unroll
                    for (int mt = 0; mt < 4; mt++) {
                        int row = wm * 64 + mt * 16 + (mat & 1) * 8 + mr;
                        uint32_t off = (uint32_t)(row << 7) + ks * 32 + (mat >> 1) * 16;
                        uint32_t sw = off ^ ((off >> 3) & 0x70);
                        ldm_x4(af[mt], base + sw);
                    }
                    #pragma unroll
                    for (int bq = 0; bq < 2; bq++) {
                        int nrow = wn * 32 + (bq * 2 + (mat >> 1)) * 8 + mr;
                        uint32_t off = (uint32_t)(nrow << 7) + ks * 32 + (mat & 1) * 16;
                        uint32_t sw = off ^ ((off >> 3) & 0x70);
                        ldm_x4(bf1[bq], base + 16384 + sw);
                        ldm_x4(bf3[bq], base + 32768 + sw);
                    }
                    if (h == 0 && ks == 0) {
                        // fold interleaved under the pair's first mma of each acc tile
                        #pragma unroll
                        for (int mt = 0; mt < 4; mt++)
                            #pragma unroll
                            for (int nt = 0; nt < 4; nt++) {
                                accg[mt][nt][0] *= rr1; accg[mt][nt][1] *= rr1;
                                accg[mt][nt][2] *= rr1; accg[mt][nt][3] *= rr1;
                                mma_f16(accg[mt][nt], af[mt], &bf1[nt >> 1][(nt & 1) * 2]);
                                accu[mt][nt][0] *= rr3; accu[mt][nt][1] *= rr3;
                                accu[mt][nt][2] *= rr3; accu[mt][nt][3] *= rr3;
                                mma_f16(accu[mt][nt], af[mt], &bf3[nt >> 1][(nt & 1) * 2]);
                            }
                    } else {
                        #pragma unroll
                        for (int mt = 0; mt < 4; mt++)
                            #pragma unroll
                            for (int nt = 0; nt < 4; nt++) {
                                mma_f16(accg[mt][nt], af[mt], &bf1[nt >> 1][(nt & 1) * 2]);
                                mma_f16(accu[mt][nt], af[mt], &bf3[nt >> 1][(nt & 1) * 2]);
                            }
                    }
                }
            }
        }

        // epilogue: act = silu(g * s1) * (u * s3), fp16 stores (g,u never touch memory)
        #pragma unroll
        for (int mt = 0; mt < 4; mt++) {
            int r0 = bm * 128 + wm * 64 + mt * 16 + g;
            #pragma unroll
            for (int nt = 0; nt < 4; nt++) {
                int c0 = bn * 128 + wn * 32 + nt * 8 + t4 * 2;
                float g0 = accg[mt][nt][0] * s1_cur, g1 = accg[mt][nt][1] * s1_cur;
                float g2 = accg[mt][nt][2] * s1_cur, g3 = accg[mt][nt][3] * s1_cur;
                float u0 = accu[mt][nt][0] * s3_cur, u1 = accu[mt][nt][1] * s3_cur;
                float u2 = accu[mt][nt][2] * s3_cur, u3 = accu[mt][nt][3] * s3_cur;
                __half2 h0 = __floats2half2_rn(silu_f(g0) * u0, silu_f(g1) * u1);
                __half2 h1 = __floats2half2_rn(silu_f(g2) * u2, silu_f(g3) * u3);
                *reinterpret_cast<__half2*>(&Act[(size_t)r0 * N + c0]) = h0;
                *reinterpret_cast<__half2*>(&Act[(size_t)(r0 + 8) * N + c0]) = h1;
            }
        }
    }
}

// ============ GEMM3: R14-validated persistent 128x256 kernel (byte-identical body) ==========
__global__ __launch_bounds__(256, 1)
void gemm_f16(const __half* __restrict__ A,
              const __half* __restrict__ B0, const float* __restrict__ S0, void* __restrict__ C0,
              int M, int N, int K, int out_half)
{
    extern __shared__ char smem[];
    const uint32_t sb = smem_u32(smem);
    const int tid = threadIdx.x;
    const int wid = tid >> 5, lane = tid & 31;
    const int wm = wid & 1, wn = wid >> 1;       // 2 x 4 warps, 64x64 warp tiles
    const int mat = lane >> 3, mr = lane & 7;
    const int g = lane >> 2, t4 = lane & 3;

    const int GM = M >> 7;
    const int GN = N >> 8;
    const int NP = K >> 7;
    const int total = GM * GN;

    for (int t = blockIdx.x; t < total; t += gridDim.x) {
        const int bn = t / GM;
        const int bm = t - bn * GM;

        const __half* Ab = A + (size_t)bm * 128 * K;
        const __half* Bb = B0 + (size_t)bn * 256 * K;
        const float* Srow = S0 + (size_t)(bn * 2 + (wn >> 1)) * NP;

        auto load_pair = [&](int p) {
            #pragma unroll
            for (int h = 0; h < 2; h++) {
                const uint32_t ab = sb + ((p & 1) * 2 + h) * STB;
                const uint32_t bb = ab + AST;
                const int k0 = (p << 7) + (h << 6);
                #pragma unroll
                for (int tt = 0; tt < 4; tt++) {
                    int idx = tid + tt * 256;
                    int row = idx >> 3, c = idx & 7;
                    uint32_t off = (uint32_t)(row << 7) + (c << 4);
                    uint32_t sw = off ^ ((off >> 3) & 0x70);
                    cp_async16(ab + sw, Ab + (size_t)row * K + k0 + c * 8);
                }
                #pragma unroll
                for (int tt = 0; tt < 8; tt++) {
                    int idx = tid + tt * 256;
                    int row = idx >> 3, c = idx & 7;
                    uint32_t off = (uint32_t)(row << 7) + (c << 4);
                    uint32_t sw = off ^ ((off >> 3) & 0x70);
                    cp_async16(bb + sw, Bb + (size_t)row * K + k0 + c * 8);
                }
            }
            cp_commit();
        };

        float acc[4][8][4];
        #pragma unroll
        for (int mt = 0; mt < 4; mt++)
            #pragma unroll
            for (int nt = 0; nt < 8; nt++)
                #pragma unroll
                for (int i = 0; i < 4; i++) acc[mt][nt][i] = 0.0f;

        load_pair(0);
        float s_cur = __ldg(Srow);

        for (int p = 0; p < NP; p++) {
            float rr = 1.0f;
            if (p) {
                float sn = __ldg(Srow + p);
                rr = s_cur / sn;
                s_cur = sn;
            }

            cp_wait<0>();
            __syncthreads();

            if (p + 1 < NP) load_pair(p + 1);

            #pragma unroll
            for (int h = 0; h < 2; h++) {
                const uint32_t ab = sb + ((p & 1) * 2 + h) * STB;
                const uint32_t bb = ab + AST;
                #pragma unroll
                for (int ks = 0; ks < 4; ks++) {
                    uint32_t af[4][4], bf[4][4];
                    #pragma unroll
                    for (int mt = 0; mt < 4; mt++) {
                        int row = wm * 64 + mt * 16 + (mat & 1) * 8 + mr;
                        uint32_t off = (uint32_t)(row << 7) + ks * 32 + (mat >> 1) * 16;
                        uint32_t sw = off ^ ((off >> 3) & 0x70);
                        ldm_x4(af[mt], ab + sw);
                    }
                    #pragma unroll
                    for (int bq = 0; bq < 4; bq++) {
                        int nrow = wn * 64 + (bq * 2 + (mat >> 1)) * 8 + mr;
                        uint32_t off = (uint32_t)(nrow << 7) + ks * 32 + (mat & 1) * 16;
                        uint32_t sw = off ^ ((off >> 3) & 0x70);
                        ldm_x4(bf[bq], bb + sw);
                    }
                    if (h == 0 && ks == 0) {
                        #pragma unroll
                        for (int mt = 0; mt < 4; mt++)
                            #pragma unroll
                            for (int nt = 0; nt < 8; nt++) {
                                acc[mt][nt][0] *= rr;
                                acc[mt][nt][1] *= rr;
                                acc[mt][nt][2] *= rr;
                                acc[mt][nt][3] *= rr;
                                mma_f16(acc[mt][nt], af[mt], &bf[nt >> 1][(nt & 1) * 2]);
                            }
                    } else {
                        #pragma unroll
                        for (int mt = 0; mt < 4; mt++)
                            #pragma unroll
                            for (int nt = 0; nt < 8; nt++)
                                mma_f16(acc[mt][nt], af[mt], &bf[nt >> 1][(nt & 1) * 2]);
                    }
                }
            }
        }

        if (out_half) {
            __half* Ch = (__half*)C0;
            #pragma unroll
            for (int mt = 0; mt < 4; mt++) {
                int r0 = bm * 128 + wm * 64 + mt * 16 + g;
                #pragma unroll
                for (int nt = 0; nt < 8; nt++) {
                    int c0 = bn * 256 + wn * 64 + nt * 8 + t4 * 2;
                    __half2 h0 = __floats2half2_rn(acc[mt][nt][0] * s_cur, acc[mt][nt][1] * s_cur);
                    __half2 h1 = __floats2half2_rn(acc[mt][nt][2] * s_cur, acc[mt][nt][3] * s_cur);
                    *reinterpret_cast<__half2*>(&Ch[(size_t)r0 * N + c0]) = h0;
                    *reinterpret_cast<__half2*>(&Ch[(size_t)(r0 + 8) * N + c0]) = h1;
                }
            }
        } else {
            float* Cf = (float*)C0;
            #pragma unroll
            for (int mt = 0; mt < 4; mt++) {
                int r0 = bm * 128 + wm * 64 + mt * 16 + g;
                #pragma unroll
                for (int nt = 0; nt < 8; nt++) {
                    int c0 = bn * 256 + wn * 64 + nt * 8 + t4 * 2;
                    float2 v0 = make_float2(acc[mt][nt][0] * s_cur, acc[mt][nt][1] * s_cur);
                    float2 v1 = make_float2(acc[mt][nt][2] * s_cur, acc[mt][nt][3] * s_cur);
                    *reinterpret_cast<float2*>(&Cf[(size_t)r0 * N + c0]) = v0;
                    *reinterpret_cast<float2*>(&Cf[(size_t)(r0 + 8) * N + c0]) = v1;
                }
            }
        }
    }
}

// ---------------- launch ----------------
extern "C" void kernel_launch(void* const* d_in, const int* in_sizes, int n_in,
                              void* d_out, int out_size) {
    (void)in_sizes; (void)n_in; (void)out_size;
    const float* x   = (const float*)d_in[0];
    const float* w1q = (const float*)d_in[1];
    const float* w1s = (const float*)d_in[2];
    const float* w3q = (const float*)d_in[3];
    const float* w3s = (const float*)d_in[4];
    const float* w2q = (const float*)d_in[5];
    const float* w2s = (const float*)d_in[6];
    float* out = (float*)d_out;

    __half *xh, *w1h, *w3h, *w2h, *acth;
    cudaGetSymbolAddress((void**)&xh,   d_xh);
    cudaGetSymbolAddress((void**)&w1h,  d_w1h);
    cudaGetSymbolAddress((void**)&w3h,  d_w3h);
    cudaGetSymbolAddress((void**)&w2h,  d_w2h);
    cudaGetSymbolAddress((void**)&acth, d_acth);

    int nsm = 148;
    cudaDeviceGetAttribute(&nsm, cudaDevAttrMultiProcessorCount, 0);

    cudaFuncSetAttribute(gemm12_fused, cudaFuncAttributeMaxDynamicSharedMemorySize, SMEMF);
    cudaFuncSetAttribute(gemm_f16, cudaFuncAttributeMaxDynamicSharedMemorySize, SMEMB);

    // one fused convert launch: x + w1 + w3 + w2 (4 float4 per thread)
    const int n4tot = N4X + 3 * N4W;
    cvt_all_kernel<<<(n4tot + 1023) / 1024, 256>>>(
        (const float4*)x,   (uint2*)xh,
        (const float4*)w1q, (uint2*)w1h,
        (const float4*)w3q, (uint2*)w3h,
        (const float4*)w2q, (uint2*)w2h, n4tot);

    // act = silu(x@w1^T) * (x@w3^T)  — fused in-register, fp16 out, persistent
    {
        const int tiles = (TDIM / 128) * (FDIM / 128);
        const int grid = tiles < nsm ? tiles : nsm;
        gemm12_fused<<<grid, 256, SMEMF>>>(xh, w1h, w1s, w3h, w3s, acth,
                                           TDIM, FDIM, HDIM);
    }

    // out = act @ w2^T  (fp32 out, persistent)
    {
        const int tiles = (TDIM / 128) * (HDIM / 256);
        const int grid = tiles < nsm ? tiles : nsm;
        gemm_f16<<<grid, 256, SMEMB>>>(acth, w2h, w2s, out, TDIM, HDIM, FDIM, 0);
    }
}